// round 13
// baseline (speedup 1.0000x reference)
#include <cuda_runtime.h>
#include <math.h>
#include <mma.h>

using namespace nvcuda;

#define NN 100000
#define EE 1600000

// ---------------- device scratch ----------------
__device__ int   g_cnt[NN];
__device__ int   g_off[NN + 1];
__device__ int   g_cursor[NN];
__device__ int   g_part[512];
__device__ int   g_csr_src[EE];
__device__ float g_dinv[NN];
__device__ __align__(16) float g_aggx[NN * 64];   // full A = agg + self
__device__ __align__(16) float g_hg[NN * 64];
__device__ __align__(16) float g_g[NN * 64];
__device__ float g_ssrc[NN], g_sdst[NN];
__device__ float g_U2[80 * 64], g_C2[80];
__device__ float g_W2[64 * 64], g_B2[64];
__device__ float g_Dacc[80];
__device__ __align__(16) float g_Znum[80 * 64];
__device__ __align__(16) float g_avec[64];

__device__ __forceinline__ void redAdd4(float4* p, float4 v) {
    asm volatile("red.global.add.v4.f32 [%0], {%1,%2,%3,%4};"
                 :: "l"(p), "f"(v.x), "f"(v.y), "f"(v.z), "f"(v.w) : "memory");
}

__device__ __forceinline__ float to_tf32(float x) {
    float r;
    asm("cvt.rna.tf32.f32 %0, %1;" : "=f"(r) : "f"(x));
    return r;
}

// ---------------- zero small stuff + degree counters ----------------
__global__ void k_zero() {
    int idx = blockIdx.x * 256 + threadIdx.x;   // 391 blocks
    if (idx < NN) g_cnt[idx] = 0;
    if (idx < 80 * 64) g_Znum[idx] = 0.f;
    if (idx < 80) g_Dacc[idx] = 0.f;
}

__global__ void k_cnt(const int* __restrict__ ei) {
    int e = blockIdx.x * 256 + threadIdx.x;     // EE exactly
    atomicAdd(&g_cnt[ei[EE + e]], 1);
}

// ---------------- scan (3 kernels) ----------------
__global__ void k_scan1() {
    __shared__ int sd[256];
    int idx = blockIdx.x * 256 + threadIdx.x;
    int v = (idx < NN) ? g_cnt[idx] : 0;
    sd[threadIdx.x] = v;
    __syncthreads();
    for (int off = 128; off > 0; off >>= 1) {
        if (threadIdx.x < off) sd[threadIdx.x] += sd[threadIdx.x + off];
        __syncthreads();
    }
    if (threadIdx.x == 0) g_part[blockIdx.x] = sd[0];
}

__global__ void k_scan2b() {
    __shared__ int sd[512];
    int t = threadIdx.x;
    int v = (t < 391) ? g_part[t] : 0;
    sd[t] = v;
    __syncthreads();
    int acc = v;
    for (int off = 1; off < 512; off <<= 1) {
        int tmp = (t >= off) ? sd[t - off] : 0;
        __syncthreads();
        acc += tmp; sd[t] = acc;
        __syncthreads();
    }
    if (t < 391) g_part[t] = acc - v;   // exclusive
}

__global__ void k_scan3() {
    __shared__ int sd[256];
    int t = threadIdx.x;
    int idx = blockIdx.x * 256 + t;
    int v = (idx < NN) ? g_cnt[idx] : 0;
    sd[t] = v;
    __syncthreads();
    int acc = v;
    for (int off = 1; off < 256; off <<= 1) {
        int tmp = (t >= off) ? sd[t - off] : 0;
        __syncthreads();
        acc += tmp; sd[t] = acc;
        __syncthreads();
    }
    if (idx < NN) {
        int off_g = acc - v + g_part[blockIdx.x];
        g_off[idx] = off_g;
        g_cursor[idx] = off_g;
        g_dinv[idx] = rsqrtf((float)(v + 1));
        if (idx == NN - 1) g_off[NN] = off_g + v;
    }
}

// ---------------- CSR fill ----------------
__global__ void k_fill(const int* __restrict__ ei) {
    int e = blockIdx.x * 256 + threadIdx.x;     // EE exactly
    int s = ei[e], d = ei[EE + e];
    int pos = atomicAdd(&g_cursor[d], 1);
    g_csr_src[pos] = s;
}

// ---------------- GCN gather: A = sum_e w*x[src] + x*dinv^2, warp/node ----------------
__global__ void __launch_bounds__(256) k_gcn_gather(const float* __restrict__ x) {
    int w = (blockIdx.x * 256 + threadIdx.x) >> 5;   // node, grid 12500 -> exact
    int lane = threadIdx.x & 31;
    int beg = g_off[w], end = g_off[w + 1];
    float din = g_dinv[w];
    const float2* x2 = (const float2*)x;
    float2 xv = x2[w * 32 + lane];
    float d2 = din * din;
    float2 acc = make_float2(xv.x * d2, xv.y * d2);
    for (int c = beg; c < end; c += 32) {
        int m = end - c; if (m > 32) m = 32;
        int sidx = 0; float sd = 0.f;
        if (c + lane < end) { sidx = g_csr_src[c + lane]; sd = g_dinv[sidx]; }
        for (int j = 0; j < m; j++) {
            int s = __shfl_sync(0xffffffffu, sidx, j);
            float wgt = __shfl_sync(0xffffffffu, sd, j) * din;
            float2 v = x2[s * 32 + lane];
            acc.x += wgt * v.x; acc.y += wgt * v.y;
        }
    }
    ((float2*)g_aggx)[w * 32 + lane] = acc;
}

// ---------------- small kernel 1: fold tiny matrices ----------------
__global__ void k_small1(const float* __restrict__ superQ,
                         const float* __restrict__ in_w, const float* __restrict__ in_b,
                         const float* __restrict__ gcnK_W, const float* __restrict__ gcnK_b,
                         const float* __restrict__ gcnV_W, const float* __restrict__ gcnV_b,
                         const float* __restrict__ gat_W) {
    __shared__ float s_qh[640];
    __shared__ float s_u[5120];
    __shared__ float s_c0[80];
    int t = threadIdx.x;
    const float scale = 0.35355339059327373f;  // 1/sqrt(8)
    for (int i = t; i < 640; i += 256) {
        int l = i >> 6, ii = i & 63;
        float acc = in_b[ii];
        for (int k = 0; k < 64; k++) acc += superQ[l * 64 + k] * in_w[ii * 64 + k];
        s_qh[i] = acc * scale;
    }
    __syncthreads();
    for (int i = t; i < 5120; i += 256) {
        int c = i >> 6, k = i & 63;
        int h = c / 10, l = c % 10;
        float acc = 0.f;
        for (int j = 0; j < 8; j++)
            acc += s_qh[l * 64 + h * 8 + j] * in_w[(64 + h * 8 + j) * 64 + k];
        s_u[i] = acc;
    }
    if (t < 80) {
        int h = t / 10, l = t % 10;
        float acc = 0.f;
        for (int j = 0; j < 8; j++) acc += s_qh[l * 64 + h * 8 + j] * in_b[64 + h * 8 + j];
        s_c0[t] = acc;
    }
    __syncthreads();
    for (int i = t; i < 5120; i += 256) {
        int c = i >> 6, kp = i & 63;
        float acc = 0.f;
        for (int k = 0; k < 64; k++) acc += gcnK_W[kp * 64 + k] * s_u[c * 64 + k];
        g_U2[i] = acc;
    }
    if (t < 80) {
        float acc = s_c0[t];
        for (int k = 0; k < 64; k++) acc += gcnK_b[k] * s_u[t * 64 + k];
        g_C2[t] = acc;
    }
    for (int i = t; i < 4096; i += 256) {
        int kp = i >> 6, j = i & 63;
        float acc = 0.f;
        for (int k = 0; k < 64; k++) acc += gcnV_W[kp * 64 + k] * gat_W[k * 64 + j];
        g_W2[i] = acc;
    }
    if (t < 64) {
        float acc = 0.f;
        for (int k = 0; k < 64; k++) acc += gcnV_b[k] * gat_W[k * 64 + t];
        g_B2[t] = acc;
    }
}

// ---------------- fused node pass via tf32 tensor cores ----------------
// sA [80][72], sU [80][72] (U2, later reused as Znum staging), sW [64][64],
// sE [80][88], sHG [80][72], sC [80], sB2 [64]
#define NODEA_SMEM ((80*72 + 80*72 + 64*64 + 80*88 + 80*72 + 80 + 64) * 4)
__global__ void __launch_bounds__(256) k_nodeA_tc() {
    extern __shared__ float sm[];
    float* sA  = sm;                 // [80][72]
    float* sU  = sA + 80 * 72;       // [80][72]
    float* sW  = sU + 80 * 72;       // [64][64]
    float* sE  = sW + 4096;          // [80][88]
    float* sHG = sE + 80 * 88;       // [80][72]
    float* sC  = sHG + 80 * 72;      // [80]
    float* sB2 = sC + 80;            // [64]

    int t = threadIdx.x;
    int warp = t >> 5;               // 0..7
    int n0 = blockIdx.x * 80;

    for (int i = t; i < 4096; i += 256) sW[i] = g_W2[i];
    for (int i = t; i < 5120; i += 256) { int c = i >> 6, k = i & 63; sU[c * 72 + k] = g_U2[i]; }
    if (t < 80) sC[t] = g_C2[t];
    if (t < 64) sB2[t] = g_B2[t];
    for (int i = t; i < 1280; i += 256) {
        int r = i >> 4, q = i & 15;
        *(float4*)&sA[r * 72 + q * 4] = ((const float4*)g_aggx)[(n0 + r) * 16 + q];
    }
    __syncthreads();

    // ---- phase 1: hg = A @ W2 -> sHG (20 tiles) ----
    for (int tt = warp; tt < 20; tt += 8) {
        int r = tt / 4, col = tt & 3;
        wmma::fragment<wmma::accumulator, 16, 16, 8, float> c;
        wmma::fill_fragment(c, 0.f);
        for (int k = 0; k < 8; k++) {
            wmma::fragment<wmma::matrix_a, 16, 16, 8, wmma::precision::tf32, wmma::row_major> ah, al;
            wmma::fragment<wmma::matrix_b, 16, 16, 8, wmma::precision::tf32, wmma::row_major> bh, bl;
            wmma::load_matrix_sync(ah, sA + r * 16 * 72 + k * 8, 72);
            wmma::load_matrix_sync(bh, sW + k * 8 * 64 + col * 16, 64);
#pragma unroll
            for (int i = 0; i < ah.num_elements; i++) {
                float v = ah.x[i]; float h = to_tf32(v);
                ah.x[i] = h; al.x[i] = to_tf32(v - h);
            }
#pragma unroll
            for (int i = 0; i < bh.num_elements; i++) {
                float v = bh.x[i]; float h = to_tf32(v);
                bh.x[i] = h; bl.x[i] = to_tf32(v - h);
            }
            wmma::mma_sync(c, ah, bh, c);
            wmma::mma_sync(c, al, bh, c);
            wmma::mma_sync(c, ah, bl, c);
        }
        wmma::store_matrix_sync(sHG + r * 16 * 72 + col * 16, c, 72, wmma::mem_row_major);
    }

    // ---- phase 2: S = A @ U2^T -> sE (25 tiles; U2 as col_major B) ----
    for (int tt = warp; tt < 25; tt += 8) {
        int r = tt / 5, col = tt % 5;
        wmma::fragment<wmma::accumulator, 16, 16, 8, float> c;
        wmma::fill_fragment(c, 0.f);
        for (int k = 0; k < 8; k++) {
            wmma::fragment<wmma::matrix_a, 16, 16, 8, wmma::precision::tf32, wmma::row_major> ah, al;
            wmma::fragment<wmma::matrix_b, 16, 16, 8, wmma::precision::tf32, wmma::col_major> bh, bl;
            wmma::load_matrix_sync(ah, sA + r * 16 * 72 + k * 8, 72);
            wmma::load_matrix_sync(bh, sU + col * 16 * 72 + k * 8, 72);
#pragma unroll
            for (int i = 0; i < ah.num_elements; i++) {
                float v = ah.x[i]; float h = to_tf32(v);
                ah.x[i] = h; al.x[i] = to_tf32(v - h);
            }
#pragma unroll
            for (int i = 0; i < bh.num_elements; i++) {
                float v = bh.x[i]; float h = to_tf32(v);
                bh.x[i] = h; bl.x[i] = to_tf32(v - h);
            }
            wmma::mma_sync(c, ah, bh, c);
            wmma::mma_sync(c, al, bh, c);
            wmma::mma_sync(c, ah, bl, c);
        }
        wmma::store_matrix_sync(sE + r * 16 * 88 + col * 16, c, 88, wmma::mem_row_major);
    }
    __syncthreads();

    // elementwise: sE = exp(sE + c2); write hg = sHG + B2 to global
    for (int i = t; i < 6400; i += 256) {
        int r = i / 80, c = i % 80;
        sE[r * 88 + c] = __expf(sE[r * 88 + c] + sC[c]);
    }
    for (int i = t; i < 1280; i += 256) {
        int r = i >> 4, q = i & 15;
        float4 v = *(float4*)&sHG[r * 72 + q * 4];
        float4 b = *(float4*)&sB2[q * 4];
        v.x += b.x; v.y += b.y; v.z += b.z; v.w += b.w;
        ((float4*)g_hg)[(n0 + r) * 16 + q] = v;
    }
    __syncthreads();

    // ---- phase 3: Znum = E^T @ A -> sU staging (20 tiles; E^T via col_major A) ----
    for (int tt = warp; tt < 20; tt += 8) {
        int ct = tt / 4, kt = tt & 3;
        wmma::fragment<wmma::accumulator, 16, 16, 8, float> c;
        wmma::fill_fragment(c, 0.f);
        for (int n = 0; n < 10; n++) {
            wmma::fragment<wmma::matrix_a, 16, 16, 8, wmma::precision::tf32, wmma::col_major> ah, al;
            wmma::fragment<wmma::matrix_b, 16, 16, 8, wmma::precision::tf32, wmma::row_major> bh, bl;
            wmma::load_matrix_sync(ah, sE + n * 8 * 88 + ct * 16, 88);
            wmma::load_matrix_sync(bh, sA + n * 8 * 72 + kt * 16, 72);
#pragma unroll
            for (int i = 0; i < ah.num_elements; i++) {
                float v = ah.x[i]; float h = to_tf32(v);
                ah.x[i] = h; al.x[i] = to_tf32(v - h);
            }
#pragma unroll
            for (int i = 0; i < bh.num_elements; i++) {
                float v = bh.x[i]; float h = to_tf32(v);
                bh.x[i] = h; bl.x[i] = to_tf32(v - h);
            }
            wmma::mma_sync(c, ah, bh, c);
            wmma::mma_sync(c, al, bh, c);
            wmma::mma_sync(c, ah, bl, c);
        }
        wmma::store_matrix_sync(sU + ct * 16 * 72 + kt * 16, c, 72, wmma::mem_row_major);
    }
    __syncthreads();

    // red-add Znum staging to global; Dacc colsum
    for (int i = t; i < 1280; i += 256) {
        int r = i >> 4, q = i & 15;
        redAdd4(&((float4*)g_Znum)[r * 16 + q], *(float4*)&sU[r * 72 + q * 4]);
    }
    if (t < 80) {
        float s = 0.f;
        for (int r = 0; r < 80; r++) s += sE[r * 88 + t];
        atomicAdd(&g_Dacc[t], s);
    }
}

// ---------------- small kernel 2 ----------------
__global__ void k_small2(const float* __restrict__ in_w, const float* __restrict__ in_b,
                         const float* __restrict__ out_w, const float* __restrict__ out_b,
                         const float* __restrict__ gcnV_W, const float* __restrict__ gcnV_b,
                         const float* __restrict__ gat_Wc, const float* __restrict__ a_src) {
    __shared__ float s_zA[5120];
    __shared__ float s_zV[5120];
    __shared__ float s_o[640];
    __shared__ float s_mo[64];
    __shared__ float s_ctx[64];
    int t = threadIdx.x;  // 128
    for (int i = t; i < 5120; i += 128) s_zA[i] = g_Znum[i] / g_Dacc[i >> 6];
    __syncthreads();
    for (int i = t; i < 5120; i += 128) {
        int c = i >> 6, k = i & 63;
        float acc = gcnV_b[k];
        for (int kp = 0; kp < 64; kp++) acc += s_zA[c * 64 + kp] * gcnV_W[kp * 64 + k];
        s_zV[i] = acc;
    }
    __syncthreads();
    for (int i = t; i < 640; i += 128) {
        int l = i >> 6, ii = i & 63;
        int c = (ii >> 3) * 10 + l;
        float acc = in_b[128 + ii];
        for (int k = 0; k < 64; k++) acc += s_zV[c * 64 + k] * in_w[(128 + ii) * 64 + k];
        s_o[i] = acc;
    }
    __syncthreads();
    if (t < 64) {
        float acc = 0.f;
        for (int l = 0; l < 10; l++) acc += s_o[l * 64 + t];
        s_mo[t] = acc * 0.1f;
    }
    __syncthreads();
    if (t < 64) {
        float acc = out_b[t];
        for (int i = 0; i < 64; i++) acc += s_mo[i] * out_w[t * 64 + i];
        s_ctx[t] = acc;
    }
    __syncthreads();
    if (t < 64) {
        float acc = a_src[t];
        for (int kp = 0; kp < 64; kp++) acc += s_ctx[kp] * gat_Wc[kp * 64 + t];
        g_avec[t] = acc;
    }
}

// ---------------- GAT node scores ----------------
__global__ void k_sdots(const float* __restrict__ a_dst) {
    int w = blockIdx.x * 8 + (threadIdx.x >> 5);
    int lane = threadIdx.x & 31;
    if (w >= NN) return;
    float2 h  = ((const float2*)g_hg)[w * 32 + lane];
    float2 av = ((const float2*)g_avec)[lane];
    float2 ad = ((const float2*)a_dst)[lane];
    float p1 = h.x * av.x + h.y * av.y;
    float p2 = h.x * ad.x + h.y * ad.y;
#pragma unroll
    for (int off = 16; off; off >>= 1) {
        p1 += __shfl_down_sync(0xffffffffu, p1, off);
        p2 += __shfl_down_sync(0xffffffffu, p2, off);
    }
    if (lane == 0) { g_ssrc[w] = p1; g_sdst[w] = p2; }
}

// ---------------- GAT gather: softmax + weighted hg gather, one warp/node ----------------
__global__ void __launch_bounds__(256) k_gat_gather(const float* __restrict__ gat_b) {
    int w = (blockIdx.x * 256 + threadIdx.x) >> 5;   // grid 12500 -> exact
    int lane = threadIdx.x & 31;
    int beg = g_off[w], end = g_off[w + 1];
    float sdv = g_sdst[w];

    int sidx0 = 0; float ex0 = 0.f;
    if (beg + lane < end) {
        sidx0 = g_csr_src[beg + lane];
        float v = g_ssrc[sidx0] + sdv;
        v = (v >= 0.f) ? v : 0.2f * v;
        ex0 = __expf(v);
    }
    float den = ex0;
    for (int c = beg + 32; c < end; c += 32) {
        float ex = 0.f;
        if (c + lane < end) {
            int s = g_csr_src[c + lane];
            float v = g_ssrc[s] + sdv;
            v = (v >= 0.f) ? v : 0.2f * v;
            ex = __expf(v);
        }
        den += ex;
    }
#pragma unroll
    for (int off = 16; off; off >>= 1) den += __shfl_xor_sync(0xffffffffu, den, off);
    float rden = 1.f / (den + 1e-16f);

    const float2* hg2 = (const float2*)g_hg;
    float2 bb = ((const float2*)gat_b)[lane];
    float2 acc = make_float2(bb.x, bb.y);
    {
        int m = end - beg; if (m > 32) m = 32;
        for (int j = 0; j < m; j++) {
            int s = __shfl_sync(0xffffffffu, sidx0, j);
            float a = __shfl_sync(0xffffffffu, ex0, j) * rden;
            float2 hv = hg2[s * 32 + lane];
            acc.x += a * hv.x; acc.y += a * hv.y;
        }
    }
    for (int c = beg + 32; c < end; c += 32) {
        int m = end - c; if (m > 32) m = 32;
        int sidx = 0; float ex = 0.f;
        if (c + lane < end) {
            sidx = g_csr_src[c + lane];
            float v = g_ssrc[sidx] + sdv;
            v = (v >= 0.f) ? v : 0.2f * v;
            ex = __expf(v);
        }
        for (int j = 0; j < m; j++) {
            int s = __shfl_sync(0xffffffffu, sidx, j);
            float a = __shfl_sync(0xffffffffu, ex, j) * rden;
            float2 hv = hg2[s * 32 + lane];
            acc.x += a * hv.x; acc.y += a * hv.y;
        }
    }
    ((float2*)g_g)[w * 32 + lane] = acc;
}

// ---------------- fused MLP via tf32 tensor cores ----------------
#define MLP_SMEM ((64*128 + 128*64 + 80*72 + 80*136) * 4)
__global__ void __launch_bounds__(256) k_mlp_tc(const float* __restrict__ t1_W, const float* __restrict__ t1_b,
                                                const float* __restrict__ t2_W, const float* __restrict__ t2_b,
                                                float* __restrict__ out) {
    extern __shared__ float sm[];
    float* sW1 = sm;              // [64][128]
    float* sW2 = sW1 + 8192;      // [128][64]
    float* sG  = sW2 + 8192;      // [80][72]
    float* sH  = sG + 80 * 72;    // [80][136]

    int t = threadIdx.x;
    int warp = t >> 5;            // 0..7
    int n0 = blockIdx.x * 80;

    for (int i = t; i < 8192; i += 256) { sW1[i] = t1_W[i]; sW2[i] = t2_W[i]; }
    for (int i = t; i < 1280; i += 256) {
        int r = i >> 4, q = i & 15;
        *(float4*)&sG[r * 72 + q * 4] = ((const float4*)g_g)[(n0 + r) * 16 + q];
    }
    __syncthreads();

    {
        wmma::fragment<wmma::accumulator, 16, 16, 8, float> c[5];
#pragma unroll
        for (int r = 0; r < 5; r++) wmma::fill_fragment(c[r], 0.f);
        int col = warp;
        for (int k = 0; k < 8; k++) {
            wmma::fragment<wmma::matrix_b, 16, 16, 8, wmma::precision::tf32, wmma::row_major> bh, bl;
            wmma::load_matrix_sync(bh, sW1 + k * 8 * 128 + col * 16, 128);
#pragma unroll
            for (int i = 0; i < bh.num_elements; i++) {
                float v = bh.x[i]; float h = to_tf32(v);
                bh.x[i] = h; bl.x[i] = to_tf32(v - h);
            }
#pragma unroll
            for (int r = 0; r < 5; r++) {
                wmma::fragment<wmma::matrix_a, 16, 16, 8, wmma::precision::tf32, wmma::row_major> ah, al;
                wmma::load_matrix_sync(ah, sG + r * 16 * 72 + k * 8, 72);
#pragma unroll
                for (int i = 0; i < ah.num_elements; i++) {
                    float v = ah.x[i]; float h = to_tf32(v);
                    ah.x[i] = h; al.x[i] = to_tf32(v - h);
                }
                wmma::mma_sync(c[r], ah, bh, c[r]);
                wmma::mma_sync(c[r], al, bh, c[r]);
                wmma::mma_sync(c[r], ah, bl, c[r]);
            }
        }
#pragma unroll
        for (int r = 0; r < 5; r++)
            wmma::store_matrix_sync(sH + r * 16 * 136 + warp * 16, c[r], 136, wmma::mem_row_major);
    }
    __syncthreads();

    for (int i = t; i < 10240; i += 256) {
        int r = i >> 7, cc = i & 127;
        sH[r * 136 + cc] = fmaxf(sH[r * 136 + cc] + t1_b[cc], 0.f);
    }
    __syncthreads();

    for (int tt = warp; tt < 20; tt += 8) {
        int r = tt >> 2, col = tt & 3;
        wmma::fragment<wmma::accumulator, 16, 16, 8, float> c;
        wmma::fill_fragment(c, 0.f);
        for (int k = 0; k < 16; k++) {
            wmma::fragment<wmma::matrix_b, 16, 16, 8, wmma::precision::tf32, wmma::row_major> bh, bl;
            wmma::load_matrix_sync(bh, sW2 + k * 8 * 64 + col * 16, 64);
#pragma unroll
            for (int i = 0; i < bh.num_elements; i++) {
                float v = bh.x[i]; float h = to_tf32(v);
                bh.x[i] = h; bl.x[i] = to_tf32(v - h);
            }
            wmma::fragment<wmma::matrix_a, 16, 16, 8, wmma::precision::tf32, wmma::row_major> ah, al;
            wmma::load_matrix_sync(ah, sH + r * 16 * 136 + k * 8, 136);
#pragma unroll
            for (int i = 0; i < ah.num_elements; i++) {
                float v = ah.x[i]; float h = to_tf32(v);
                ah.x[i] = h; al.x[i] = to_tf32(v - h);
            }
            wmma::mma_sync(c, ah, bh, c);
            wmma::mma_sync(c, al, bh, c);
            wmma::mma_sync(c, ah, bl, c);
        }
        wmma::store_matrix_sync(sG + r * 16 * 72 + col * 16, c, 72, wmma::mem_row_major);
    }
    __syncthreads();

    for (int i = t; i < 5120; i += 256) {
        int r = i >> 6, cc = i & 63;
        out[(n0 + r) * 64 + cc] = fmaxf(sG[r * 72 + cc] + t2_b[cc], 0.f);
    }
}

// ---------------- launch ----------------
extern "C" void kernel_launch(void* const* d_in, const int* in_sizes, int n_in,
                              void* d_out, int out_size) {
    const float* x        = (const float*)d_in[0];
    const int*   ei       = (const int*)d_in[1];
    const float* gcnK_W   = (const float*)d_in[2];
    const float* gcnK_b   = (const float*)d_in[3];
    const float* gcnV_W   = (const float*)d_in[4];
    const float* gcnV_b   = (const float*)d_in[5];
    const float* super_Q  = (const float*)d_in[6];
    const float* mha_in_w = (const float*)d_in[7];
    const float* mha_in_b = (const float*)d_in[8];
    const float* mha_out_w= (const float*)d_in[9];
    const float* mha_out_b= (const float*)d_in[10];
    const float* gat_W    = (const float*)d_in[11];
    const float* gat_Wc   = (const float*)d_in[12];
    const float* gat_a_src= (const float*)d_in[13];
    const float* gat_a_dst= (const float*)d_in[14];
    const float* gat_b    = (const float*)d_in[15];
    const float* t1_W     = (const float*)d_in[16];
    const float* t1_b     = (const float*)d_in[17];
    const float* t2_W     = (const float*)d_in[18];
    const float* t2_b     = (const float*)d_in[19];
    float* out = (float*)d_out;

    cudaFuncSetAttribute(k_nodeA_tc, cudaFuncAttributeMaxDynamicSharedMemorySize, NODEA_SMEM);
    cudaFuncSetAttribute(k_mlp_tc,   cudaFuncAttributeMaxDynamicSharedMemorySize, MLP_SMEM);

    k_zero<<<391, 256>>>();
    k_cnt<<<6250, 256>>>(ei);
    k_scan1<<<391, 256>>>();
    k_scan2b<<<1, 512>>>();
    k_scan3<<<391, 256>>>();
    k_fill<<<6250, 256>>>(ei);
    k_gcn_gather<<<12500, 256>>>(x);
    k_small1<<<1, 256>>>(super_Q, mha_in_w, mha_in_b, gcnK_W, gcnK_b,
                         gcnV_W, gcnV_b, gat_W);
    k_nodeA_tc<<<1250, 256, NODEA_SMEM>>>();
    k_small2<<<1, 128>>>(mha_in_w, mha_in_b, mha_out_w, mha_out_b,
                         gcnV_W, gcnV_b, gat_Wc, gat_a_src);
    k_sdots<<<12500, 256>>>(gat_a_dst);
    k_gat_gather<<<12500, 256>>>(gat_b);
    k_mlp_tc<<<1250, 256, MLP_SMEM>>>(t1_W, t1_b, t2_W, t2_b, out);
}

// round 17
// speedup vs baseline: 1.1099x; 1.1099x over previous
#include <cuda_runtime.h>
#include <math.h>
#include <mma.h>

using namespace nvcuda;

#define NN 100000
#define EE 1600000

// ---------------- device scratch ----------------
__device__ int   g_cnt[NN];
__device__ int   g_off[NN + 1];
__device__ int   g_cursor[NN];
__device__ int   g_part[512];
__device__ int   g_csr_src[EE];
__device__ float g_dinv[NN];
__device__ __align__(16) float g_aggx[NN * 64];   // full A = agg + self
__device__ __align__(16) float g_hg[NN * 64];
__device__ __align__(16) float g_g[NN * 64];
__device__ float g_ssrc[NN], g_sdst[NN];
__device__ float g_U2[80 * 64], g_C2[80];
__device__ float g_W2[64 * 64], g_B2[64];
__device__ float g_Dacc[80];
__device__ __align__(16) float g_Znum[80 * 64];
__device__ __align__(16) float g_avec[64];

__device__ __forceinline__ void redAdd4(float4* p, float4 v) {
    asm volatile("red.global.add.v4.f32 [%0], {%1,%2,%3,%4};"
                 :: "l"(p), "f"(v.x), "f"(v.y), "f"(v.z), "f"(v.w) : "memory");
}

__device__ __forceinline__ float to_tf32(float x) {
    float r;
    asm("cvt.rna.tf32.f32 %0, %1;" : "=f"(r) : "f"(x));
    return r;
}

// ---------------- zero small stuff + degree counters ----------------
__global__ void k_zero() {
    int idx = blockIdx.x * 256 + threadIdx.x;   // 391 blocks
    if (idx < NN) g_cnt[idx] = 0;
    if (idx < 80 * 64) g_Znum[idx] = 0.f;
    if (idx < 80) g_Dacc[idx] = 0.f;
}

__global__ void k_cnt(const int* __restrict__ ei) {
    int e = blockIdx.x * 256 + threadIdx.x;     // EE exactly
    atomicAdd(&g_cnt[ei[EE + e]], 1);
}

// ---------------- scan (3 kernels) ----------------
__global__ void k_scan1() {
    __shared__ int sd[256];
    int idx = blockIdx.x * 256 + threadIdx.x;
    int v = (idx < NN) ? g_cnt[idx] : 0;
    sd[threadIdx.x] = v;
    __syncthreads();
    for (int off = 128; off > 0; off >>= 1) {
        if (threadIdx.x < off) sd[threadIdx.x] += sd[threadIdx.x + off];
        __syncthreads();
    }
    if (threadIdx.x == 0) g_part[blockIdx.x] = sd[0];
}

__global__ void k_scan2b() {
    __shared__ int sd[512];
    int t = threadIdx.x;
    int v = (t < 391) ? g_part[t] : 0;
    sd[t] = v;
    __syncthreads();
    int acc = v;
    for (int off = 1; off < 512; off <<= 1) {
        int tmp = (t >= off) ? sd[t - off] : 0;
        __syncthreads();
        acc += tmp; sd[t] = acc;
        __syncthreads();
    }
    if (t < 391) g_part[t] = acc - v;   // exclusive
}

__global__ void k_scan3() {
    __shared__ int sd[256];
    int t = threadIdx.x;
    int idx = blockIdx.x * 256 + t;
    int v = (idx < NN) ? g_cnt[idx] : 0;
    sd[t] = v;
    __syncthreads();
    int acc = v;
    for (int off = 1; off < 256; off <<= 1) {
        int tmp = (t >= off) ? sd[t - off] : 0;
        __syncthreads();
        acc += tmp; sd[t] = acc;
        __syncthreads();
    }
    if (idx < NN) {
        int off_g = acc - v + g_part[blockIdx.x];
        g_off[idx] = off_g;
        g_cursor[idx] = off_g;
        g_dinv[idx] = rsqrtf((float)(v + 1));
        if (idx == NN - 1) g_off[NN] = off_g + v;
    }
}

// ---------------- CSR fill ----------------
__global__ void k_fill(const int* __restrict__ ei) {
    int e = blockIdx.x * 256 + threadIdx.x;     // EE exactly
    int s = ei[e], d = ei[EE + e];
    int pos = atomicAdd(&g_cursor[d], 1);
    g_csr_src[pos] = s;
}

// ---------------- GCN gather: dual-accumulator broadcast loop ----------------
__global__ void __launch_bounds__(256) k_gcn_gather(const float* __restrict__ x) {
    int w = (blockIdx.x * 256 + threadIdx.x) >> 5;   // node, grid 12500 -> exact
    int lane = threadIdx.x & 31;
    int beg = g_off[w], end = g_off[w + 1];
    float din = g_dinv[w];
    const float2* x2 = (const float2*)x;
    float2 xv = x2[w * 32 + lane];
    float d2 = din * din;
    float2 acc0 = make_float2(xv.x * d2, xv.y * d2);
    float2 acc1 = make_float2(0.f, 0.f);
    for (int c = beg; c < end; c += 32) {
        int m = end - c; if (m > 32) m = 32;
        int sidx = 0; float sd = 0.f;
        if (c + lane < end) { sidx = g_csr_src[c + lane]; sd = g_dinv[sidx]; }
        int j = 0;
        for (; j + 1 < m; j += 2) {
            int s0 = __shfl_sync(0xffffffffu, sidx, j);
            float w0 = __shfl_sync(0xffffffffu, sd, j) * din;
            int s1 = __shfl_sync(0xffffffffu, sidx, j + 1);
            float w1 = __shfl_sync(0xffffffffu, sd, j + 1) * din;
            float2 v0 = x2[s0 * 32 + lane];
            float2 v1 = x2[s1 * 32 + lane];
            acc0.x += w0 * v0.x; acc0.y += w0 * v0.y;
            acc1.x += w1 * v1.x; acc1.y += w1 * v1.y;
        }
        if (j < m) {
            int s0 = __shfl_sync(0xffffffffu, sidx, j);
            float w0 = __shfl_sync(0xffffffffu, sd, j) * din;
            float2 v0 = x2[s0 * 32 + lane];
            acc0.x += w0 * v0.x; acc0.y += w0 * v0.y;
        }
    }
    acc0.x += acc1.x; acc0.y += acc1.y;
    ((float2*)g_aggx)[w * 32 + lane] = acc0;
}

// ---------------- small kernel 1: fold tiny matrices ----------------
__global__ void k_small1(const float* __restrict__ superQ,
                         const float* __restrict__ in_w, const float* __restrict__ in_b,
                         const float* __restrict__ gcnK_W, const float* __restrict__ gcnK_b,
                         const float* __restrict__ gcnV_W, const float* __restrict__ gcnV_b,
                         const float* __restrict__ gat_W) {
    __shared__ float s_qh[640];
    __shared__ float s_u[5120];
    __shared__ float s_c0[80];
    int t = threadIdx.x;
    const float scale = 0.35355339059327373f;  // 1/sqrt(8)
    for (int i = t; i < 640; i += 256) {
        int l = i >> 6, ii = i & 63;
        float acc = in_b[ii];
        for (int k = 0; k < 64; k++) acc += superQ[l * 64 + k] * in_w[ii * 64 + k];
        s_qh[i] = acc * scale;
    }
    __syncthreads();
    for (int i = t; i < 5120; i += 256) {
        int c = i >> 6, k = i & 63;
        int h = c / 10, l = c % 10;
        float acc = 0.f;
        for (int j = 0; j < 8; j++)
            acc += s_qh[l * 64 + h * 8 + j] * in_w[(64 + h * 8 + j) * 64 + k];
        s_u[i] = acc;
    }
    if (t < 80) {
        int h = t / 10, l = t % 10;
        float acc = 0.f;
        for (int j = 0; j < 8; j++) acc += s_qh[l * 64 + h * 8 + j] * in_b[64 + h * 8 + j];
        s_c0[t] = acc;
    }
    __syncthreads();
    for (int i = t; i < 5120; i += 256) {
        int c = i >> 6, kp = i & 63;
        float acc = 0.f;
        for (int k = 0; k < 64; k++) acc += gcnK_W[kp * 64 + k] * s_u[c * 64 + k];
        g_U2[i] = acc;
    }
    if (t < 80) {
        float acc = s_c0[t];
        for (int k = 0; k < 64; k++) acc += gcnK_b[k] * s_u[t * 64 + k];
        g_C2[t] = acc;
    }
    for (int i = t; i < 4096; i += 256) {
        int kp = i >> 6, j = i & 63;
        float acc = 0.f;
        for (int k = 0; k < 64; k++) acc += gcnV_W[kp * 64 + k] * gat_W[k * 64 + j];
        g_W2[i] = acc;
    }
    if (t < 64) {
        float acc = 0.f;
        for (int k = 0; k < 64; k++) acc += gcnV_b[k] * gat_W[k * 64 + t];
        g_B2[t] = acc;
    }
}

// ---------------- fused node pass: hg GEMM + MHA S/exp + Znum/Dacc (SIMT) ----------------
#define SA_STR 68
#define SE_STR 84
#define NODEA_SMEM ((80*SA_STR + 80*SA_STR + 64*64 + 80*SE_STR + 80 + 64) * 4)
__global__ void __launch_bounds__(256) k_nodeA() {
    extern __shared__ float sm[];
    float* sA    = sm;                       // [80][68]
    float* sU    = sA + 80 * SA_STR;         // [80][68]
    float* sW    = sU + 80 * SA_STR;         // [64][64]
    float* sE    = sW + 64 * 64;             // [80][84]
    float* sC    = sE + 80 * SE_STR;         // [80]
    float* sB2   = sC + 80;                  // [64]

    int t = threadIdx.x;
    int n0 = blockIdx.x * 80;

    for (int i = t; i < 4096; i += 256) sW[i] = g_W2[i];
    for (int i = t; i < 5120; i += 256) { int c = i >> 6, k = i & 63; sU[c * SA_STR + k] = g_U2[i]; }
    if (t < 80) sC[t] = g_C2[t];
    if (t < 64) sB2[t] = g_B2[t];
#pragma unroll
    for (int i = 0; i < 5; i++) {
        int idx = t + 256 * i, r = idx >> 4, q = idx & 15;
        *(float4*)&sA[r * SA_STR + q * 4] = ((const float4*)g_aggx)[(n0 + r) * 16 + q];
    }
    __syncthreads();

    // phase hg
    {
        int rq = t >> 4, cg = t & 15;
        float4 acc[5];
        float4 b = *(float4*)&sB2[cg * 4];
#pragma unroll
        for (int i = 0; i < 5; i++) acc[i] = b;
        for (int k = 0; k < 64; k++) {
            float4 wv = *(float4*)&sW[k * 64 + cg * 4];
#pragma unroll
            for (int i = 0; i < 5; i++) {
                float a = sA[(rq * 5 + i) * SA_STR + k];
                acc[i].x += a * wv.x; acc[i].y += a * wv.y;
                acc[i].z += a * wv.z; acc[i].w += a * wv.w;
            }
        }
#pragma unroll
        for (int i = 0; i < 5; i++)
            *(float4*)&g_hg[(n0 + rq * 5 + i) * 64 + cg * 4] = acc[i];
    }

    // phase S/E
    {
        int rq = t >> 4, cgrp = t & 15;
        float acc[5][5];
#pragma unroll
        for (int j = 0; j < 5; j++) {
            float c0 = sC[cgrp * 5 + j];
#pragma unroll
            for (int i = 0; i < 5; i++) acc[i][j] = c0;
        }
        for (int k = 0; k < 64; k++) {
            float a[5], u[5];
#pragma unroll
            for (int i = 0; i < 5; i++) a[i] = sA[(rq * 5 + i) * SA_STR + k];
#pragma unroll
            for (int j = 0; j < 5; j++) u[j] = sU[(cgrp * 5 + j) * SA_STR + k];
#pragma unroll
            for (int i = 0; i < 5; i++)
#pragma unroll
                for (int j = 0; j < 5; j++) acc[i][j] += a[i] * u[j];
        }
#pragma unroll
        for (int i = 0; i < 5; i++)
#pragma unroll
            for (int j = 0; j < 5; j++)
                sE[(rq * 5 + i) * SE_STR + cgrp * 5 + j] = __expf(acc[i][j]);
    }
    __syncthreads();

    // phase Znum
    {
        int cq = t >> 4, kg = t & 15;
        float4 z[5];
#pragma unroll
        for (int j = 0; j < 5; j++) z[j] = make_float4(0.f, 0.f, 0.f, 0.f);
        for (int r = 0; r < 80; r++) {
            float4 a = *(float4*)&sA[r * SA_STR + kg * 4];
#pragma unroll
            for (int j = 0; j < 5; j++) {
                float e = sE[r * SE_STR + cq * 5 + j];
                z[j].x += e * a.x; z[j].y += e * a.y;
                z[j].z += e * a.z; z[j].w += e * a.w;
            }
        }
#pragma unroll
        for (int j = 0; j < 5; j++)
            redAdd4((float4*)&g_Znum[(cq * 5 + j) * 64 + kg * 4], z[j]);
    }
    if (t < 80) {
        float s = 0.f;
        for (int r = 0; r < 80; r++) s += sE[r * SE_STR + t];
        atomicAdd(&g_Dacc[t], s);
    }
}

// ---------------- small kernel 2 ----------------
__global__ void k_small2(const float* __restrict__ in_w, const float* __restrict__ in_b,
                         const float* __restrict__ out_w, const float* __restrict__ out_b,
                         const float* __restrict__ gcnV_W, const float* __restrict__ gcnV_b,
                         const float* __restrict__ gat_Wc, const float* __restrict__ a_src) {
    __shared__ float s_zA[5120];
    __shared__ float s_zV[5120];
    __shared__ float s_o[640];
    __shared__ float s_mo[64];
    __shared__ float s_ctx[64];
    int t = threadIdx.x;  // 128
    for (int i = t; i < 5120; i += 128) s_zA[i] = g_Znum[i] / g_Dacc[i >> 6];
    __syncthreads();
    for (int i = t; i < 5120; i += 128) {
        int c = i >> 6, k = i & 63;
        float acc = gcnV_b[k];
        for (int kp = 0; kp < 64; kp++) acc += s_zA[c * 64 + kp] * gcnV_W[kp * 64 + k];
        s_zV[i] = acc;
    }
    __syncthreads();
    for (int i = t; i < 640; i += 128) {
        int l = i >> 6, ii = i & 63;
        int c = (ii >> 3) * 10 + l;
        float acc = in_b[128 + ii];
        for (int k = 0; k < 64; k++) acc += s_zV[c * 64 + k] * in_w[(128 + ii) * 64 + k];
        s_o[i] = acc;
    }
    __syncthreads();
    if (t < 64) {
        float acc = 0.f;
        for (int l = 0; l < 10; l++) acc += s_o[l * 64 + t];
        s_mo[t] = acc * 0.1f;
    }
    __syncthreads();
    if (t < 64) {
        float acc = out_b[t];
        for (int i = 0; i < 64; i++) acc += s_mo[i] * out_w[t * 64 + i];
        s_ctx[t] = acc;
    }
    __syncthreads();
    if (t < 64) {
        float acc = a_src[t];
        for (int kp = 0; kp < 64; kp++) acc += s_ctx[kp] * gat_Wc[kp * 64 + t];
        g_avec[t] = acc;
    }
}

// ---------------- GAT node scores ----------------
__global__ void k_sdots(const float* __restrict__ a_dst) {
    int w = blockIdx.x * 8 + (threadIdx.x >> 5);
    int lane = threadIdx.x & 31;
    if (w >= NN) return;
    float2 h  = ((const float2*)g_hg)[w * 32 + lane];
    float2 av = ((const float2*)g_avec)[lane];
    float2 ad = ((const float2*)a_dst)[lane];
    float p1 = h.x * av.x + h.y * av.y;
    float p2 = h.x * ad.x + h.y * ad.y;
#pragma unroll
    for (int off = 16; off; off >>= 1) {
        p1 += __shfl_down_sync(0xffffffffu, p1, off);
        p2 += __shfl_down_sync(0xffffffffu, p2, off);
    }
    if (lane == 0) { g_ssrc[w] = p1; g_sdst[w] = p2; }
}

// ---------------- GAT gather: dual-accumulator weighted gather ----------------
__global__ void __launch_bounds__(256) k_gat_gather(const float* __restrict__ gat_b) {
    int w = (blockIdx.x * 256 + threadIdx.x) >> 5;   // grid 12500 -> exact
    int lane = threadIdx.x & 31;
    int beg = g_off[w], end = g_off[w + 1];
    float sdv = g_sdst[w];

    // phase A: denominator; cache chunk 0
    int sidx0 = 0; float ex0 = 0.f;
    if (beg + lane < end) {
        sidx0 = g_csr_src[beg + lane];
        float v = g_ssrc[sidx0] + sdv;
        v = (v >= 0.f) ? v : 0.2f * v;
        ex0 = __expf(v);
    }
    float den = ex0;
    for (int c = beg + 32; c < end; c += 32) {
        float ex = 0.f;
        if (c + lane < end) {
            int s = g_csr_src[c + lane];
            float v = g_ssrc[s] + sdv;
            v = (v >= 0.f) ? v : 0.2f * v;
            ex = __expf(v);
        }
        den += ex;
    }
#pragma unroll
    for (int off = 16; off; off >>= 1) den += __shfl_xor_sync(0xffffffffu, den, off);
    float rden = 1.f / (den + 1e-16f);

    // phase B: weighted gather of hg rows, dual accumulators
    const float2* hg2 = (const float2*)g_hg;
    float2 bb = ((const float2*)gat_b)[lane];
    float2 acc0 = make_float2(bb.x, bb.y);
    float2 acc1 = make_float2(0.f, 0.f);
    // chunk 0 from registers
    {
        int m = end - beg; if (m > 32) m = 32;
        int j = 0;
        for (; j + 1 < m; j += 2) {
            int s0 = __shfl_sync(0xffffffffu, sidx0, j);
            float a0 = __shfl_sync(0xffffffffu, ex0, j) * rden;
            int s1 = __shfl_sync(0xffffffffu, sidx0, j + 1);
            float a1 = __shfl_sync(0xffffffffu, ex0, j + 1) * rden;
            float2 h0 = hg2[s0 * 32 + lane];
            float2 h1 = hg2[s1 * 32 + lane];
            acc0.x += a0 * h0.x; acc0.y += a0 * h0.y;
            acc1.x += a1 * h1.x; acc1.y += a1 * h1.y;
        }
        if (j < m) {
            int s0 = __shfl_sync(0xffffffffu, sidx0, j);
            float a0 = __shfl_sync(0xffffffffu, ex0, j) * rden;
            float2 h0 = hg2[s0 * 32 + lane];
            acc0.x += a0 * h0.x; acc0.y += a0 * h0.y;
        }
    }
    for (int c = beg + 32; c < end; c += 32) {
        int m = end - c; if (m > 32) m = 32;
        int sidx = 0; float ex = 0.f;
        if (c + lane < end) {
            sidx = g_csr_src[c + lane];
            float v = g_ssrc[sidx] + sdv;
            v = (v >= 0.f) ? v : 0.2f * v;
            ex = __expf(v);
        }
        int j = 0;
        for (; j + 1 < m; j += 2) {
            int s0 = __shfl_sync(0xffffffffu, sidx, j);
            float a0 = __shfl_sync(0xffffffffu, ex, j) * rden;
            int s1 = __shfl_sync(0xffffffffu, sidx, j + 1);
            float a1 = __shfl_sync(0xffffffffu, ex, j + 1) * rden;
            float2 h0 = hg2[s0 * 32 + lane];
            float2 h1 = hg2[s1 * 32 + lane];
            acc0.x += a0 * h0.x; acc0.y += a0 * h0.y;
            acc1.x += a1 * h1.x; acc1.y += a1 * h1.y;
        }
        if (j < m) {
            int s0 = __shfl_sync(0xffffffffu, sidx, j);
            float a0 = __shfl_sync(0xffffffffu, ex, j) * rden;
            float2 h0 = hg2[s0 * 32 + lane];
            acc0.x += a0 * h0.x; acc0.y += a0 * h0.y;
        }
    }
    acc0.x += acc1.x; acc0.y += acc1.y;
    ((float2*)g_g)[w * 32 + lane] = acc0;
}

// ---------------- fused MLP via tf32 tensor cores ----------------
#define MLP_SMEM ((64*128 + 128*64 + 80*72 + 80*136) * 4)
__global__ void __launch_bounds__(256) k_mlp_tc(const float* __restrict__ t1_W, const float* __restrict__ t1_b,
                                                const float* __restrict__ t2_W, const float* __restrict__ t2_b,
                                                float* __restrict__ out) {
    extern __shared__ float sm[];
    float* sW1 = sm;              // [64][128]
    float* sW2 = sW1 + 8192;      // [128][64]
    float* sG  = sW2 + 8192;      // [80][72]
    float* sH  = sG + 80 * 72;    // [80][136]

    int t = threadIdx.x;
    int warp = t >> 5;            // 0..7
    int n0 = blockIdx.x * 80;

    for (int i = t; i < 8192; i += 256) { sW1[i] = t1_W[i]; sW2[i] = t2_W[i]; }
    for (int i = t; i < 1280; i += 256) {
        int r = i >> 4, q = i & 15;
        *(float4*)&sG[r * 72 + q * 4] = ((const float4*)g_g)[(n0 + r) * 16 + q];
    }
    __syncthreads();

    {
        wmma::fragment<wmma::accumulator, 16, 16, 8, float> c[5];
#pragma unroll
        for (int r = 0; r < 5; r++) wmma::fill_fragment(c[r], 0.f);
        int col = warp;
        for (int k = 0; k < 8; k++) {
            wmma::fragment<wmma::matrix_b, 16, 16, 8, wmma::precision::tf32, wmma::row_major> bh, bl;
            wmma::load_matrix_sync(bh, sW1 + k * 8 * 128 + col * 16, 128);
#pragma unroll
            for (int i = 0; i < bh.num_elements; i++) {
                float v = bh.x[i]; float h = to_tf32(v);
                bh.x[i] = h; bl.x[i] = to_tf32(v - h);
            }
#pragma unroll
            for (int r = 0; r < 5; r++) {
                wmma::fragment<wmma::matrix_a, 16, 16, 8, wmma::precision::tf32, wmma::row_major> ah, al;
                wmma::load_matrix_sync(ah, sG + r * 16 * 72 + k * 8, 72);
#pragma unroll
                for (int i = 0; i < ah.num_elements; i++) {
                    float v = ah.x[i]; float h = to_tf32(v);
                    ah.x[i] = h; al.x[i] = to_tf32(v - h);
                }
                wmma::mma_sync(c[r], ah, bh, c[r]);
                wmma::mma_sync(c[r], al, bh, c[r]);
                wmma::mma_sync(c[r], ah, bl, c[r]);
            }
        }
#pragma unroll
        for (int r = 0; r < 5; r++)
            wmma::store_matrix_sync(sH + r * 16 * 136 + warp * 16, c[r], 136, wmma::mem_row_major);
    }
    __syncthreads();

    for (int i = t; i < 10240; i += 256) {
        int r = i >> 7, cc = i & 127;
        sH[r * 136 + cc] = fmaxf(sH[r * 136 + cc] + t1_b[cc], 0.f);
    }
    __syncthreads();

    for (int tt = warp; tt < 20; tt += 8) {
        int r = tt >> 2, col = tt & 3;
        wmma::fragment<wmma::accumulator, 16, 16, 8, float> c;
        wmma::fill_fragment(c, 0.f);
        for (int k = 0; k < 16; k++) {
            wmma::fragment<wmma::matrix_b, 16, 16, 8, wmma::precision::tf32, wmma::row_major> bh, bl;
            wmma::load_matrix_sync(bh, sW2 + k * 8 * 64 + col * 16, 64);
#pragma unroll
            for (int i = 0; i < bh.num_elements; i++) {
                float v = bh.x[i]; float h = to_tf32(v);
                bh.x[i] = h; bl.x[i] = to_tf32(v - h);
            }
            wmma::fragment<wmma::matrix_a, 16, 16, 8, wmma::precision::tf32, wmma::row_major> ah, al;
            wmma::load_matrix_sync(ah, sH + r * 16 * 136 + k * 8, 136);
#pragma unroll
            for (int i = 0; i < ah.num_elements; i++) {
                float v = ah.x[i]; float h = to_tf32(v);
                ah.x[i] = h; al.x[i] = to_tf32(v - h);
            }
            wmma::mma_sync(c, ah, bh, c);
            wmma::mma_sync(c, al, bh, c);
            wmma::mma_sync(c, ah, bl, c);
        }
        wmma::store_matrix_sync(sG + r * 16 * 72 + col * 16, c, 72, wmma::mem_row_major);
    }
    __syncthreads();

    for (int i = t; i < 5120; i += 256) {
        int r = i >> 6, cc = i & 63;
        out[(n0 + r) * 64 + cc] = fmaxf(sG[r * 72 + cc] + t2_b[cc], 0.f);
    }
}

// ---------------- launch ----------------
extern "C" void kernel_launch(void* const* d_in, const int* in_sizes, int n_in,
                              void* d_out, int out_size) {
    const float* x        = (const float*)d_in[0];
    const int*   ei       = (const int*)d_in[1];
    const float* gcnK_W   = (const float*)d_in[2];
    const float* gcnK_b   = (const float*)d_in[3];
    const float* gcnV_W   = (const float*)d_in[4];
    const float* gcnV_b   = (const float*)d_in[5];
    const float* super_Q  = (const float*)d_in[6];
    const float* mha_in_w = (const float*)d_in[7];
    const float* mha_in_b = (const float*)d_in[8];
    const float* mha_out_w= (const float*)d_in[9];
    const float* mha_out_b= (const float*)d_in[10];
    const float* gat_W    = (const float*)d_in[11];
    const float* gat_Wc   = (const float*)d_in[12];
    const float* gat_a_src= (const float*)d_in[13];
    const float* gat_a_dst= (const float*)d_in[14];
    const float* gat_b    = (const float*)d_in[15];
    const float* t1_W     = (const float*)d_in[16];
    const float* t1_b     = (const float*)d_in[17];
    const float* t2_W     = (const float*)d_in[18];
    const float* t2_b     = (const float*)d_in[19];
    float* out = (float*)d_out;

    cudaFuncSetAttribute(k_nodeA,  cudaFuncAttributeMaxDynamicSharedMemorySize, NODEA_SMEM);
    cudaFuncSetAttribute(k_mlp_tc, cudaFuncAttributeMaxDynamicSharedMemorySize, MLP_SMEM);

    k_zero<<<391, 256>>>();
    k_cnt<<<6250, 256>>>(ei);
    k_scan1<<<391, 256>>>();
    k_scan2b<<<1, 512>>>();
    k_scan3<<<391, 256>>>();
    k_fill<<<6250, 256>>>(ei);
    k_gcn_gather<<<12500, 256>>>(x);
    k_small1<<<1, 256>>>(super_Q, mha_in_w, mha_in_b, gcnK_W, gcnK_b,
                         gcnV_W, gcnV_b, gat_W);
    k_nodeA<<<1250, 256, NODEA_SMEM>>>();
    k_small2<<<1, 128>>>(mha_in_w, mha_in_b, mha_out_w, mha_out_b,
                         gcnV_W, gcnV_b, gat_Wc, gat_a_src);
    k_sdots<<<12500, 256>>>(gat_a_dst);
    k_gat_gather<<<12500, 256>>>(gat_b);
    k_mlp_tc<<<1250, 256, MLP_SMEM>>>(t1_W, t1_b, t2_W, t2_b, out);
}